// round 1
// baseline (speedup 1.0000x reference)
#include <cuda_runtime.h>
#include <math.h>

// Problem constants
#define BB 2
#define HH 12
#define NN 4096
#define DD 64
#define CC 768
#define C3 2304
#define MM (BB*NN)      // 8192 tokens
#define ATT_SCALE 0.125f

// Scratch (device globals -- no allocations allowed)
__device__ float g_Q[(size_t)BB*HH*NN*DD];   // [B,H,N,D], pre-scaled
__device__ float g_K[(size_t)BB*HH*NN*DD];
__device__ float g_V[(size_t)BB*HH*NN*DD];
__device__ float g_AO[(size_t)BB*NN*CC];     // attention output [B,N,C]

// ---------------------------------------------------------------------------
// Kernel 1: QKV = x @ w_qkv^T, scattered into Q(scaled)/K/V in [B,H,N,D]
//   x: [8192, 768] row-major, w: [2304, 768] row-major (out x in)
// 64x64 output tile, BK=16, 256 threads, 4x4 per thread.
// ---------------------------------------------------------------------------
__global__ __launch_bounds__(256) void qkv_gemm(const float* __restrict__ x,
                                                const float* __restrict__ w) {
    __shared__ float As[16][65];   // [k][m]
    __shared__ float Bs[16][65];   // [k][o]
    const int m0 = blockIdx.y * 64;
    const int o0 = blockIdx.x * 64;
    const int tid = threadIdx.x;
    const int tx = tid & 15, ty = tid >> 4;
    const int lr = tid >> 2;            // 0..63 (row within tile to load)
    const int lc = (tid & 3) * 4;       // 0,4,8,12 (k offset)

    float acc[4][4] = {};

    for (int c0 = 0; c0 < CC; c0 += 16) {
        float4 av = *(const float4*)&x[(size_t)(m0 + lr) * CC + c0 + lc];
        float4 bv = *(const float4*)&w[(size_t)(o0 + lr) * CC + c0 + lc];
        As[lc+0][lr] = av.x; As[lc+1][lr] = av.y; As[lc+2][lr] = av.z; As[lc+3][lr] = av.w;
        Bs[lc+0][lr] = bv.x; Bs[lc+1][lr] = bv.y; Bs[lc+2][lr] = bv.z; Bs[lc+3][lr] = bv.w;
        __syncthreads();
        #pragma unroll
        for (int k = 0; k < 16; k++) {
            float a[4], b[4];
            #pragma unroll
            for (int i = 0; i < 4; i++) a[i] = As[k][ty*4+i];
            #pragma unroll
            for (int j = 0; j < 4; j++) b[j] = Bs[k][tx*4+j];
            #pragma unroll
            for (int i = 0; i < 4; i++)
                #pragma unroll
                for (int j = 0; j < 4; j++)
                    acc[i][j] = fmaf(a[i], b[j], acc[i][j]);
        }
        __syncthreads();
    }

    // Scatter: o = o0 + tx*4 + j. Whole 64-wide tile lies in one of Q/K/V.
    const int seg = o0 / CC;            // 0=Q, 1=K, 2=V
    const int obase = o0 % CC;
    float* dst = (seg == 0) ? g_Q : (seg == 1) ? g_K : g_V;
    const float sc = (seg == 0) ? ATT_SCALE : 1.0f;

    #pragma unroll
    for (int i = 0; i < 4; i++) {
        const int t = m0 + ty*4 + i;
        const int b = t / NN, n = t % NN;
        #pragma unroll
        for (int j = 0; j < 4; j++) {
            const int oo = obase + tx*4 + j;
            const int h = oo >> 6, d = oo & 63;
            dst[((((size_t)b*HH + h)*NN) + n)*DD + d] = acc[i][j] * sc;
        }
    }
}

// ---------------------------------------------------------------------------
// Kernel 2: Flash attention. One CTA per (64-query tile, b*h).
// 256 threads; S and PV are 64x64x64 register-blocked GEMMs via smem.
// Dynamic smem: Qs[64][65] + Ks[64][65] + Ps[64][65] + Vs[64][64]
// ---------------------------------------------------------------------------
__global__ __launch_bounds__(256) void flash_attn() {
    extern __shared__ float sm[];
    float* Qs = sm;                     // [d][i], ld 65
    float* Ks = sm + 64*65;             // [d][j], ld 65
    float* Ps = sm + 2*64*65;           // [m][i], ld 65
    float* Vs = sm + 3*64*65;           // [m][d], ld 64

    const int bh = blockIdx.y;          // 0..23
    const int q0 = blockIdx.x * 64;
    const float* Qg = g_Q + (size_t)bh * NN * DD;
    const float* Kg = g_K + (size_t)bh * NN * DD;
    const float* Vg = g_V + (size_t)bh * NN * DD;

    const int tid = threadIdx.x;
    const int tx = tid & 15, ty = tid >> 4;
    const int li = tid >> 4;            // 0..15 row for transposed loads
    const int ld4 = (tid & 15) * 4;     // d offset

    // Load Q tile transposed: Qs[d][i]
    for (int ii = li; ii < 64; ii += 16) {
        float4 v = *(const float4*)&Qg[(size_t)(q0 + ii)*DD + ld4];
        Qs[(ld4+0)*65 + ii] = v.x;
        Qs[(ld4+1)*65 + ii] = v.y;
        Qs[(ld4+2)*65 + ii] = v.z;
        Qs[(ld4+3)*65 + ii] = v.w;
    }

    float Oacc[4][4] = {};
    float m_run[4], l_run[4];
    #pragma unroll
    for (int i = 0; i < 4; i++) { m_run[i] = -INFINITY; l_run[i] = 0.0f; }

    for (int k0 = 0; k0 < NN; k0 += 64) {
        // Load K tile transposed and V tile row-major
        for (int ii = li; ii < 64; ii += 16) {
            float4 v = *(const float4*)&Kg[(size_t)(k0 + ii)*DD + ld4];
            Ks[(ld4+0)*65 + ii] = v.x;
            Ks[(ld4+1)*65 + ii] = v.y;
            Ks[(ld4+2)*65 + ii] = v.z;
            Ks[(ld4+3)*65 + ii] = v.w;
        }
        for (int off = tid*4; off < 64*64; off += 256*4) {
            *(float4*)&Vs[off] = *(const float4*)&Vg[(size_t)k0*DD + off];
        }
        __syncthreads();

        // S = Q K^T  (rows i owned by ty, cols j by tx)
        float s[4][4] = {};
        #pragma unroll 16
        for (int d = 0; d < 64; d++) {
            float a[4], b[4];
            #pragma unroll
            for (int i = 0; i < 4; i++) a[i] = Qs[d*65 + ty*4+i];
            #pragma unroll
            for (int j = 0; j < 4; j++) b[j] = Ks[d*65 + tx*4+j];
            #pragma unroll
            for (int i = 0; i < 4; i++)
                #pragma unroll
                for (int j = 0; j < 4; j++)
                    s[i][j] = fmaf(a[i], b[j], s[i][j]);
        }

        // Online softmax update (row groups = 16 lanes sharing ty)
        float tmax[4], tsum[4], alpha[4];
        #pragma unroll
        for (int i = 0; i < 4; i++) {
            float mx = s[i][0];
            mx = fmaxf(mx, s[i][1]); mx = fmaxf(mx, s[i][2]); mx = fmaxf(mx, s[i][3]);
            tmax[i] = mx;
        }
        #pragma unroll
        for (int i = 0; i < 4; i++)
            #pragma unroll
            for (int msk = 8; msk; msk >>= 1)
                tmax[i] = fmaxf(tmax[i], __shfl_xor_sync(0xffffffffu, tmax[i], msk));

        #pragma unroll
        for (int i = 0; i < 4; i++) {
            const float nm = fmaxf(m_run[i], tmax[i]);
            alpha[i] = __expf(m_run[i] - nm);
            m_run[i] = nm;
            float rs = 0.0f;
            #pragma unroll
            for (int j = 0; j < 4; j++) {
                s[i][j] = __expf(s[i][j] - nm);
                rs += s[i][j];
            }
            tsum[i] = rs;
        }
        #pragma unroll
        for (int i = 0; i < 4; i++)
            #pragma unroll
            for (int msk = 8; msk; msk >>= 1)
                tsum[i] += __shfl_xor_sync(0xffffffffu, tsum[i], msk);

        #pragma unroll
        for (int i = 0; i < 4; i++) {
            l_run[i] = l_run[i]*alpha[i] + tsum[i];
            #pragma unroll
            for (int j = 0; j < 4; j++) Oacc[i][j] *= alpha[i];
        }

        // Stage P into smem as Ps[m][i]  (m = key index = tx*4+j)
        #pragma unroll
        for (int j = 0; j < 4; j++)
            #pragma unroll
            for (int i = 0; i < 4; i++)
                Ps[(tx*4+j)*65 + ty*4+i] = s[i][j];
        __syncthreads();

        // O += P @ V
        #pragma unroll 16
        for (int m = 0; m < 64; m++) {
            float a[4], b[4];
            #pragma unroll
            for (int i = 0; i < 4; i++) a[i] = Ps[m*65 + ty*4+i];
            #pragma unroll
            for (int j = 0; j < 4; j++) b[j] = Vs[m*64 + tx*4+j];
            #pragma unroll
            for (int i = 0; i < 4; i++)
                #pragma unroll
                for (int j = 0; j < 4; j++)
                    Oacc[i][j] = fmaf(a[i], b[j], Oacc[i][j]);
        }
        __syncthreads();
    }

    // Epilogue: normalize + write [B,N,C] (head h occupies cols h*64..h*64+63)
    const int b = bh / HH, h = bh % HH;
    #pragma unroll
    for (int i = 0; i < 4; i++) {
        const float inv = 1.0f / l_run[i];
        const int n = q0 + ty*4 + i;
        #pragma unroll
        for (int j = 0; j < 4; j++)
            g_AO[((size_t)b*NN + n)*CC + h*64 + tx*4 + j] = Oacc[i][j] * inv;
    }
}

// ---------------------------------------------------------------------------
// Kernel 3: out = g_AO @ w_proj^T + b_proj   -> d_out [8192, 768]
// ---------------------------------------------------------------------------
__global__ __launch_bounds__(256) void proj_gemm(const float* __restrict__ wp,
                                                 const float* __restrict__ bias,
                                                 float* __restrict__ out) {
    __shared__ float As[16][65];
    __shared__ float Bs[16][65];
    const int m0 = blockIdx.y * 64;
    const int o0 = blockIdx.x * 64;
    const int tid = threadIdx.x;
    const int tx = tid & 15, ty = tid >> 4;
    const int lr = tid >> 2;
    const int lc = (tid & 3) * 4;

    float acc[4][4] = {};

    for (int c0 = 0; c0 < CC; c0 += 16) {
        float4 av = *(const float4*)&g_AO[(size_t)(m0 + lr) * CC + c0 + lc];
        float4 bv = *(const float4*)&wp[(size_t)(o0 + lr) * CC + c0 + lc];
        As[lc+0][lr] = av.x; As[lc+1][lr] = av.y; As[lc+2][lr] = av.z; As[lc+3][lr] = av.w;
        Bs[lc+0][lr] = bv.x; Bs[lc+1][lr] = bv.y; Bs[lc+2][lr] = bv.z; Bs[lc+3][lr] = bv.w;
        __syncthreads();
        #pragma unroll
        for (int k = 0; k < 16; k++) {
            float a[4], b[4];
            #pragma unroll
            for (int i = 0; i < 4; i++) a[i] = As[k][ty*4+i];
            #pragma unroll
            for (int j = 0; j < 4; j++) b[j] = Bs[k][tx*4+j];
            #pragma unroll
            for (int i = 0; i < 4; i++)
                #pragma unroll
                for (int j = 0; j < 4; j++)
                    acc[i][j] = fmaf(a[i], b[j], acc[i][j]);
        }
        __syncthreads();
    }

    #pragma unroll
    for (int j = 0; j < 4; j++) {
        const int o = o0 + tx*4 + j;
        const float bj = bias[o];
        #pragma unroll
        for (int i = 0; i < 4; i++) {
            const int t = m0 + ty*4 + i;
            out[(size_t)t*CC + o] = acc[i][j] + bj;
        }
    }
}

// ---------------------------------------------------------------------------
extern "C" void kernel_launch(void* const* d_in, const int* in_sizes, int n_in,
                              void* d_out, int out_size) {
    const float* x      = (const float*)d_in[0];   // [2,4096,768]
    const float* w_qkv  = (const float*)d_in[1];   // [2304,768]
    const float* w_proj = (const float*)d_in[2];   // [768,768]
    const float* b_proj = (const float*)d_in[3];   // [768]
    float* out = (float*)d_out;

    // Kernel 1: QKV projection
    {
        dim3 grid(C3/64, MM/64);   // (36, 128)
        qkv_gemm<<<grid, 256>>>(x, w_qkv);
    }

    // Kernel 2: flash attention
    {
        const int smem_bytes = (3*64*65 + 64*64) * (int)sizeof(float);  // 66304
        cudaFuncSetAttribute(flash_attn, cudaFuncAttributeMaxDynamicSharedMemorySize,
                             smem_bytes);
        dim3 grid(NN/64, BB*HH);   // (64, 24)
        flash_attn<<<grid, 256, smem_bytes>>>();
    }

    // Kernel 3: output projection + bias
    {
        dim3 grid(CC/64, MM/64);   // (12, 128)
        proj_gemm<<<grid, 256>>>(w_proj, b_proj, out);
    }
}

// round 15
// speedup vs baseline: 1.0927x; 1.0927x over previous
#include <cuda_runtime.h>
#include <math.h>

// ===========================================================================
// Attention block, fp32 FFMA (vectorized smem). Round 14 resubmission of the
// R10 design with renamed symbols (content-hash bust); semantics identical.
// ===========================================================================

// Problem constants
#define BB 2
#define HH 12
#define NN 4096
#define DD 64
#define CC 768
#define C3 2304
#define MM (BB*NN)      // 8192 tokens
#define ATT_SCALE 0.125f

// Scratch (device globals -- no allocations allowed)
__device__ float g_Qbuf[(size_t)BB*HH*NN*DD];   // [B,H,N,D], pre-scaled
__device__ float g_Kbuf[(size_t)BB*HH*NN*DD];
__device__ float g_Vbuf[(size_t)BB*HH*NN*DD];
__device__ float g_AObuf[(size_t)BB*NN*CC];     // attention output [B,N,C]

// Pad of 68 floats: row stride = 272 B (multiple of 16) -> LDS.128 fragment
// reads in every inner loop.
#define LDT 68

// ---------------------------------------------------------------------------
// Kernel 1: QKV = x @ w_qkv^T, scattered into Q(scaled)/K/V in [B,H,N,D].
// 64x64 output tile, BK=16, 256 threads, 4x4 per thread, vectorized LDS.
// ---------------------------------------------------------------------------
__global__ __launch_bounds__(256) void qkv_gemm_v2(const float* __restrict__ x,
                                                   const float* __restrict__ w) {
    __shared__ __align__(16) float As[16 * LDT];   // [k][m]
    __shared__ __align__(16) float Bs[16 * LDT];   // [k][o]
    const int m0 = blockIdx.y * 64;
    const int o0 = blockIdx.x * 64;
    const int tid = threadIdx.x;
    const int tx = tid & 15, ty = tid >> 4;
    const int lr = tid >> 2;            // 0..63: row of the tile this thread stages
    const int lc = (tid & 3) * 4;       // 0/4/8/12: k offset staged

    float acc[4][4] = {};

    for (int c0 = 0; c0 < CC; c0 += 16) {
        float4 av = *(const float4*)&x[(size_t)(m0 + lr) * CC + c0 + lc];
        float4 bv = *(const float4*)&w[(size_t)(o0 + lr) * CC + c0 + lc];
        As[(lc+0)*LDT + lr] = av.x; As[(lc+1)*LDT + lr] = av.y;
        As[(lc+2)*LDT + lr] = av.z; As[(lc+3)*LDT + lr] = av.w;
        Bs[(lc+0)*LDT + lr] = bv.x; Bs[(lc+1)*LDT + lr] = bv.y;
        Bs[(lc+2)*LDT + lr] = bv.z; Bs[(lc+3)*LDT + lr] = bv.w;
        __syncthreads();
        #pragma unroll
        for (int k = 0; k < 16; k++) {
            const float4 a4 = *(const float4*)&As[k*LDT + ty*4];
            const float4 b4 = *(const float4*)&Bs[k*LDT + tx*4];
            const float a[4] = { a4.x, a4.y, a4.z, a4.w };
            const float b[4] = { b4.x, b4.y, b4.z, b4.w };
            #pragma unroll
            for (int i = 0; i < 4; i++)
                #pragma unroll
                for (int j = 0; j < 4; j++)
                    acc[i][j] = fmaf(a[i], b[j], acc[i][j]);
        }
        __syncthreads();
    }

    // Scatter epilogue. The whole 64-wide output tile lies in one of Q/K/V.
    const int seg = o0 / CC;            // 0=Q, 1=K, 2=V
    const int obase = o0 % CC;
    float* dst = (seg == 0) ? g_Qbuf : (seg == 1) ? g_Kbuf : g_Vbuf;
    const float sc = (seg == 0) ? ATT_SCALE : 1.0f;

    #pragma unroll
    for (int i = 0; i < 4; i++) {
        const int t = m0 + ty*4 + i;
        const int b = t / NN, n = t % NN;
        #pragma unroll
        for (int j = 0; j < 4; j++) {
            const int oo = obase + tx*4 + j;
            const int h = oo >> 6, d = oo & 63;
            dst[((((size_t)b*HH + h)*NN) + n)*DD + d] = acc[i][j] * sc;
        }
    }
}

// ---------------------------------------------------------------------------
// Kernel 2: Flash attention. One CTA per (64-query tile, b*h); 256 threads.
// S and PV are 64x64x64 register-blocked GEMMs through shared memory.
// Dynamic smem: Qs[64][68] + Ks[64][68] + Ps[64][68] + Vs[64][64] = 68608 B.
// ---------------------------------------------------------------------------
#define FA_SMEM ((3*64*LDT + 64*64) * (int)sizeof(float))

__global__ __launch_bounds__(256) void flash_attn_v2() {
    extern __shared__ __align__(16) float smbuf[];
    float* Qs = smbuf;                    // [d][i], ld LDT
    float* Ks = smbuf + 64*LDT;           // [d][j], ld LDT
    float* Ps = smbuf + 2*64*LDT;         // [m][i], ld LDT
    float* Vs = smbuf + 3*64*LDT;         // [m][d], ld 64

    const int bh = blockIdx.y;            // 0..23
    const int q0 = blockIdx.x * 64;
    const float* Qg = g_Qbuf + (size_t)bh * NN * DD;
    const float* Kg = g_Kbuf + (size_t)bh * NN * DD;
    const float* Vg = g_Vbuf + (size_t)bh * NN * DD;

    const int tid = threadIdx.x;
    const int tx = tid & 15, ty = tid >> 4;
    const int li = tid >> 4;              // 0..15: row stride for transposed loads
    const int ld4 = (tid & 15) * 4;       // d offset

    // Stage Q tile transposed: Qs[d][i]
    for (int ii = li; ii < 64; ii += 16) {
        float4 v = *(const float4*)&Qg[(size_t)(q0 + ii)*DD + ld4];
        Qs[(ld4+0)*LDT + ii] = v.x;
        Qs[(ld4+1)*LDT + ii] = v.y;
        Qs[(ld4+2)*LDT + ii] = v.z;
        Qs[(ld4+3)*LDT + ii] = v.w;
    }

    float Oacc[4][4] = {};
    float m_run[4], l_run[4];
    #pragma unroll
    for (int i = 0; i < 4; i++) { m_run[i] = -INFINITY; l_run[i] = 0.0f; }

    for (int k0 = 0; k0 < NN; k0 += 64) {
        // Stage K tile transposed and V tile row-major
        for (int ii = li; ii < 64; ii += 16) {
            float4 v = *(const float4*)&Kg[(size_t)(k0 + ii)*DD + ld4];
            Ks[(ld4+0)*LDT + ii] = v.x;
            Ks[(ld4+1)*LDT + ii] = v.y;
            Ks[(ld4+2)*LDT + ii] = v.z;
            Ks[(ld4+3)*LDT + ii] = v.w;
        }
        for (int off = tid*4; off < 64*64; off += 256*4) {
            *(float4*)&Vs[off] = *(const float4*)&Vg[(size_t)k0*DD + off];
        }
        __syncthreads();

        // ---- S = Q K^T  (vectorized smem reads) ----
        float s[4][4] = {};
        #pragma unroll 16
        for (int d = 0; d < 64; d++) {
            const float4 a4 = *(const float4*)&Qs[d*LDT + ty*4];
            const float4 b4 = *(const float4*)&Ks[d*LDT + tx*4];
            const float a[4] = { a4.x, a4.y, a4.z, a4.w };
            const float b[4] = { b4.x, b4.y, b4.z, b4.w };
            #pragma unroll
            for (int i = 0; i < 4; i++)
                #pragma unroll
                for (int j = 0; j < 4; j++)
                    s[i][j] = fmaf(a[i], b[j], s[i][j]);
        }

        // ---- online softmax (row groups = 16 lanes sharing ty) ----
        float tmax[4], tsum[4], alpha[4];
        #pragma unroll
        for (int i = 0; i < 4; i++)
            tmax[i] = fmaxf(fmaxf(s[i][0], s[i][1]), fmaxf(s[i][2], s[i][3]));
        #pragma unroll
        for (int i = 0; i < 4; i++)
            #pragma unroll
            for (int msk = 8; msk; msk >>= 1)
                tmax[i] = fmaxf(tmax[i], __shfl_xor_sync(0xffffffffu, tmax[i], msk));

        #pragma unroll
        for (int i = 0; i < 4; i++) {
            const float nm = fmaxf(m_run[i], tmax[i]);
            alpha[i] = __expf(m_run[i] - nm);
            m_run[i] = nm;
            float rs = 0.0f;
            #pragma unroll
            for (int j = 0; j < 4; j++) {
                s[i][j] = __expf(s[i][j] - nm);
                rs += s[i][j];
            }
            tsum[i] = rs;
        }
        #pragma unroll
        for (int i = 0; i < 4; i++)
            #pragma unroll
            for (int msk = 8; msk; msk >>= 1)
                tsum[i] += __shfl_xor_sync(0xffffffffu, tsum[i], msk);

        #pragma unroll
        for (int i = 0; i < 4; i++) {
            l_run[i] = l_run[i]*alpha[i] + tsum[i];
            #pragma unroll
            for (int j = 0; j < 4; j++) Oacc[i][j] *= alpha[i];
        }

        // ---- stage P as Ps[m][i] (m = key idx = tx*4+j); STS.128 ----
        #pragma unroll
        for (int j = 0; j < 4; j++) {
            float4 pv = make_float4(s[0][j], s[1][j], s[2][j], s[3][j]);
            *(float4*)&Ps[(tx*4+j)*LDT + ty*4] = pv;
        }
        __syncthreads();

        // ---- O += P @ V  (vectorized smem reads) ----
        #pragma unroll 16
        for (int m = 0; m < 64; m++) {
            const float4 a4 = *(const float4*)&Ps[m*LDT + ty*4];
            const float4 b4 = *(const float4*)&Vs[m*64 + tx*4];
            const float a[4] = { a4.x, a4.y, a4.z, a4.w };
            const float b[4] = { b4.x, b4.y, b4.z, b4.w };
            #pragma unroll
            for (int i = 0; i < 4; i++)
                #pragma unroll
                for (int j = 0; j < 4; j++)
                    Oacc[i][j] = fmaf(a[i], b[j], Oacc[i][j]);
        }
        __syncthreads();
    }

    // Epilogue: normalize + write [B,N,C] (head h owns cols h*64..h*64+63)
    const int b = bh / HH, h = bh % HH;
    #pragma unroll
    for (int i = 0; i < 4; i++) {
        const float inv = 1.0f / l_run[i];
        const int n = q0 + ty*4 + i;
        #pragma unroll
        for (int j = 0; j < 4; j++)
            g_AObuf[((size_t)b*NN + n)*CC + h*64 + tx*4 + j] = Oacc[i][j] * inv;
    }
}

// ---------------------------------------------------------------------------
// Kernel 3: out = g_AO @ w_proj^T + b_proj   -> d_out [8192, 768]
// ---------------------------------------------------------------------------
__global__ __launch_bounds__(256) void proj_gemm_v2(const float* __restrict__ wp,
                                                    const float* __restrict__ bias,
                                                    float* __restrict__ out) {
    __shared__ __align__(16) float As[16 * LDT];
    __shared__ __align__(16) float Bs[16 * LDT];
    const int m0 = blockIdx.y * 64;
    const int o0 = blockIdx.x * 64;
    const int tid = threadIdx.x;
    const int tx = tid & 15, ty = tid >> 4;
    const int lr = tid >> 2;
    const int lc = (tid & 3) * 4;

    float acc[4][4] = {};

    for (int c0 = 0; c0 < CC; c0 += 16) {
        float4 av = *(const float4*)&g_AObuf[(size_t)(m0 + lr) * CC + c0 + lc];
        float4 bv = *(const float4*)&wp[(size_t)(o0 + lr) * CC + c0 + lc];
        As[(lc+0)*LDT + lr] = av.x; As[(lc+1)*LDT + lr] = av.y;
        As[(lc+2)*LDT + lr] = av.z; As[(lc+3)*LDT + lr] = av.w;
        Bs[(lc+0)*LDT + lr] = bv.x; Bs[(lc+1)*LDT + lr] = bv.y;
        Bs[(lc+2)*LDT + lr] = bv.z; Bs[(lc+3)*LDT + lr] = bv.w;
        __syncthreads();
        #pragma unroll
        for (int k = 0; k < 16; k++) {
            const float4 a4 = *(const float4*)&As[k*LDT + ty*4];
            const float4 b4 = *(const float4*)&Bs[k*LDT + tx*4];
            const float a[4] = { a4.x, a4.y, a4.z, a4.w };
            const float b[4] = { b4.x, b4.y, b4.z, b4.w };
            #pragma unroll
            for (int i = 0; i < 4; i++)
                #pragma unroll
                for (int j = 0; j < 4; j++)
                    acc[i][j] = fmaf(a[i], b[j], acc[i][j]);
        }
        __syncthreads();
    }

    #pragma unroll
    for (int j = 0; j < 4; j++) {
        const int o = o0 + tx*4 + j;
        const float bj = bias[o];
        #pragma unroll
        for (int i = 0; i < 4; i++) {
            const int t = m0 + ty*4 + i;
            out[(size_t)t*CC + o] = acc[i][j] + bj;
        }
    }
}

// ---------------------------------------------------------------------------
extern "C" void kernel_launch(void* const* d_in, const int* in_sizes, int n_in,
                              void* d_out, int out_size) {
    const float* x      = (const float*)d_in[0];   // [2,4096,768]
    const float* w_qkv  = (const float*)d_in[1];   // [2304,768]
    const float* w_proj = (const float*)d_in[2];   // [768,768]
    const float* b_proj = (const float*)d_in[3];   // [768]
    float* out = (float*)d_out;

    // Kernel 1: QKV projection
    {
        dim3 grid(C3/64, MM/64);   // (36, 128)
        qkv_gemm_v2<<<grid, 256>>>(x, w_qkv);
    }

    // Kernel 2: flash attention
    {
        cudaFuncSetAttribute(flash_attn_v2,
                             cudaFuncAttributeMaxDynamicSharedMemorySize,
                             FA_SMEM);
        dim3 grid(NN/64, BB*HH);   // (64, 24)
        flash_attn_v2<<<grid, 256, FA_SMEM>>>();
    }

    // Kernel 3: output projection + bias
    {
        dim3 grid(CC/64, MM/64);   // (12, 128)
        proj_gemm_v2<<<grid, 256>>>(w_proj, b_proj, out);
    }
}